// round 16
// baseline (speedup 1.0000x reference)
#include <cuda_runtime.h>
#include <cuda_bf16.h>
#include <cuda_fp16.h>
#include <cstdint>

#define MM 9
#define DD 128
#define NMAX 8192

// ---------------- global scratch (static, no dynamic alloc) ----------------
static __device__ __align__(128) __half g_h[NMAX * MM * DD];   // 18.9 MB fp16
static __device__ __align__(128) float fsum_g[NMAX * DD];      // 4 MB fp32

// pair index tables: pair p -> (j, k), j < k
static __device__ const int PJ_d[36] =
    {0,0,0,0,0,0,0,0, 1,1,1,1,1,1,1, 2,2,2,2,2,2, 3,3,3,3,3, 4,4,4,4, 5,5,5, 6,6, 7};
static __device__ const int PK_d[36] =
    {1,2,3,4,5,6,7,8, 2,3,4,5,6,7,8, 3,4,5,6,7,8, 4,5,6,7,8, 5,6,7,8, 6,7,8, 7,8, 8};

// ---------------- helpers ---------------------------------------------------
__device__ __forceinline__ uint32_t bswz(int row, int q) {
    int c = q >> 1;
    int cs = (c & 8) | ((c & 7) ^ (row & 7));
    return (uint32_t)(row * 256 + cs * 16 + (q & 1) * 8);
}
__device__ __forceinline__ uint32_t lmaddr(uint32_t base, int row, int chunk) {
    int cs = (chunk & 8) | ((chunk & 7) ^ (row & 7));
    return base + (uint32_t)(row * 256 + cs * 16);
}
__device__ __forceinline__ uint32_t smem_u32(const void* p) {
    uint32_t a;
    asm("{ .reg .u64 t; cvta.to.shared.u64 t, %1; cvt.u32.u64 %0, t; }" : "=r"(a) : "l"(p));
    return a;
}
#define LDSM_X4(r0, r1, r2, r3, a) \
    asm volatile("ldmatrix.sync.aligned.m8n8.x4.shared.b16 {%0,%1,%2,%3}, [%4];" \
                 : "=r"(r0), "=r"(r1), "=r"(r2), "=r"(r3) : "r"(a))
#define HMMA16(d0, d1, d2, d3, a0, a1, a2, a3, b0, b1) \
    asm volatile("mma.sync.aligned.m16n8k16.row.col.f32.f16.f16.f32 " \
                 "{%0,%1,%2,%3}, {%4,%5,%6,%7}, {%8,%9}, {%0,%1,%2,%3};" \
                 : "+f"(d0), "+f"(d1), "+f"(d2), "+f"(d3) \
                 : "r"(a0), "r"(a1), "r"(a2), "r"(a3), "r"(b0), "r"(b1))

// convert one float4 -> 4 fp16, store 8B at swizzled address
__device__ __forceinline__ void st_h4(char* base, uint32_t a, float4 v) {
    __half2 h0 = __floats2half2_rn(v.x, v.y);
    __half2 h1 = __floats2half2_rn(v.z, v.w);
    uint2 h;
    h.x = *reinterpret_cast<uint32_t*>(&h0);
    h.y = *reinterpret_cast<uint32_t*>(&h1);
    *reinterpret_cast<uint2*>(base + a) = h;
}

__device__ __forceinline__ constexpr int pidx(int j, int k) {
    return j * 8 - j * (j - 1) / 2 + (k - j - 1);
}

// ---------------- K1: n-persistent fp16 HMMA + fsum --------------------------
// grid ceil(N/32) CTAs, 256 thr; smem: W 32K | f 8K = 40K
#define SM_WH 0
#define SM_FH 32768
#define K1_SMEM 40960

__global__ void __launch_bounds__(256, 2)
k1_gemm(const float* __restrict__ F, const float* __restrict__ Wg, int N)
{
    extern __shared__ char smem[];
    const uint32_t sb = smem_u32(smem);
    const int tid  = threadIdx.x;
    const int lane = tid & 31;
    const int warp = tid >> 5;          // 0..7
    const int rg   = warp & 1;          // rows [16rg, 16rg+16)
    const int cg   = warp >> 1;         // cols [32cg, 32cg+32)
    const int n0   = blockIdx.x * 32;
    const float4* Fg4 = reinterpret_cast<const float4*>(F);
    const float4* Wg4 = reinterpret_cast<const float4*>(Wg);

    // f loader geometry: 4 float4 slots per thread (32 rows x 32 f4)
    int frow[4], fq[4];
    #pragma unroll
    for (int it = 0; it < 4; ++it) {
        int s = tid + it * 256;          // 0..1023
        frow[it] = s >> 5; fq[it] = s & 31;
    }

    // prefetch f for m = 0
    float4 fraw[4];
    #pragma unroll
    for (int it = 0; it < 4; ++it) {
        int n = n0 + frow[it];
        fraw[it] = make_float4(0.f, 0.f, 0.f, 0.f);
        if (n < N) fraw[it] = Fg4[((size_t)n * MM + 0) * 32 + fq[it]];
    }

    float4 fsum[4];
    #pragma unroll
    for (int it = 0; it < 4; ++it) fsum[it] = make_float4(0.f, 0.f, 0.f, 0.f);

    const int a_row = 16 * rg + (lane & 15);
    const int a_ch  = lane >> 4;
    const int b_rlo = (lane & 7) + ((lane >> 4) << 3);
    const int b_ch  = (lane >> 3) & 1;

    for (int m = 0; m < MM; ++m) {
        // convert W_m (fp32, L2-resident after first wave) into fp16 smem
        #pragma unroll
        for (int it = 0; it < 16; ++it) {
            int s = tid + it * 256;            // 0..4095
            int row = s >> 5, q = s & 31;
            st_h4(smem + SM_WH, bswz(row, q), Wg4[(size_t)m * 4096 + s]);
        }
        // convert f_m, accumulate fsum
        #pragma unroll
        for (int it = 0; it < 4; ++it) {
            st_h4(smem + SM_FH, bswz(frow[it], fq[it]), fraw[it]);
            fsum[it].x += fraw[it].x; fsum[it].y += fraw[it].y;
            fsum[it].z += fraw[it].z; fsum[it].w += fraw[it].w;
        }
        // prefetch next m's raw f (overlaps GEMM below)
        if (m + 1 < MM) {
            #pragma unroll
            for (int it = 0; it < 4; ++it) {
                int n = n0 + frow[it];
                float4 v = make_float4(0.f, 0.f, 0.f, 0.f);
                if (n < N) v = Fg4[((size_t)n * MM + (m + 1)) * 32 + fq[it]];
                fraw[it] = v;
            }
        }
        __syncthreads();

        float acc[4][4];
        #pragma unroll
        for (int q = 0; q < 4; ++q)
            #pragma unroll
            for (int c = 0; c < 4; ++c) acc[q][c] = 0.f;

        #pragma unroll
        for (int kk = 0; kk < 8; ++kk) {
            uint32_t a0, a1, a2, a3, bh[2][4];
            LDSM_X4(a0, a1, a2, a3, lmaddr(sb + SM_FH, a_row, 2 * kk + a_ch));
            #pragma unroll
            for (int ct = 0; ct < 2; ++ct) {
                const int brow = 32 * cg + 16 * ct + b_rlo;
                LDSM_X4(bh[ct][0], bh[ct][1], bh[ct][2], bh[ct][3],
                        lmaddr(sb + SM_WH, brow, 2 * kk + b_ch));
            }
            #pragma unroll
            for (int q = 0; q < 4; ++q) {
                const int ct = q >> 1, h = (q & 1) * 2;
                HMMA16(acc[q][0], acc[q][1], acc[q][2], acc[q][3],
                       a0, a1, a2, a3, bh[ct][h], bh[ct][h + 1]);
            }
        }

        // relu + store g as fp16
        const int r0 = n0 + 16 * rg + (lane >> 2);
        const int cb = 32 * cg + (lane & 3) * 2;
        #pragma unroll
        for (int q = 0; q < 4; ++q) {
            const int col = cb + 8 * q;
            if (r0 < N) {
                __half2 v = __floats2half2_rn(fmaxf(acc[q][0], 0.f),
                                              fmaxf(acc[q][1], 0.f));
                *reinterpret_cast<__half2*>(g_h + ((size_t)r0 * MM + m) * DD + col) = v;
            }
            if (r0 + 8 < N) {
                __half2 v = __floats2half2_rn(fmaxf(acc[q][2], 0.f),
                                              fmaxf(acc[q][3], 0.f));
                *reinterpret_cast<__half2*>(g_h + ((size_t)(r0 + 8) * MM + m) * DD + col) = v;
            }
        }
        __syncthreads();   // smem consumed; safe to overwrite next m
    }

    // store exact fp32 fsum
    float4* fd = reinterpret_cast<float4*>(fsum_g);
    #pragma unroll
    for (int it = 0; it < 4; ++it) {
        int n = n0 + frow[it];
        if (n < N) fd[(size_t)n * 32 + fq[it]] = fsum[it];
    }
}

// ---------------- K2: tensor-core Gram phase 2, 1 example per warp -----------
#define K2_WSTRIDE 5376      // stage 4096 | G 1024 | E 144 (+pad)
#define K2_SMEM (8 * K2_WSTRIDE)

__global__ void __launch_bounds__(256)
k2_phase2(float* __restrict__ out, int N)
{
    __shared__ char smem2[K2_SMEM];
    const int lane = threadIdx.x & 31;
    const int warp = threadIdx.x >> 5;
    char*  stage = smem2 + warp * K2_WSTRIDE;
    float* G = reinterpret_cast<float*>(stage + 4096);
    float* E = reinterpret_cast<float*>(stage + 5120);
    const uint32_t stage_u = smem_u32(stage);
    float4* out4 = reinterpret_cast<float4*>(out);

    const int n = blockIdx.x * 8 + warp;
    if (n >= N) return;      // warp-uniform

    const int a_row = lane & 15;
    const int a_ch  = lane >> 4;
    const int b_rlo = (lane & 7) + ((lane >> 4) << 3);
    const int b_ch  = (lane >> 3) & 1;
    const int pj1 = PJ_d[lane], pk1 = PK_d[lane];
    const int pj2 = (lane < 4) ? PJ_d[lane + 32] : 0;
    const int pk2 = (lane < 4) ? PK_d[lane + 32] : 1;

    // 0) fsum (precomputed in K1), issued first to overlap Gram
    float4 fs = reinterpret_cast<const float4*>(fsum_g)[(size_t)n * 32 + lane];

    // 1) stage g[n] (9 x 128 fp16) into swizzled smem (144 x 16B)
    const uint4* gsrc = reinterpret_cast<const uint4*>(g_h + (size_t)n * MM * DD);
    #pragma unroll
    for (int i0 = 0; i0 < 5; ++i0) {
        int i = lane + i0 * 32;
        if (i < 144) {
            int row = i >> 4, c = i & 15;
            int cs_ = (c & 8) | ((c & 7) ^ (row & 7));
            *reinterpret_cast<uint4*>(stage + row * 256 + cs_ * 16) = gsrc[i];
        }
    }
    __syncwarp();

    // 2) Gram: 8 kk x (A ldsm + B ldsm + 2 HMMA f16)
    float ac0[4] = {0.f, 0.f, 0.f, 0.f};
    float ac1[4] = {0.f, 0.f, 0.f, 0.f};
    #pragma unroll
    for (int kk = 0; kk < 8; ++kk) {
        uint32_t a0, a1, a2, a3, b0, b1, b2, b3;
        LDSM_X4(a0, a1, a2, a3, lmaddr(stage_u, a_row, 2 * kk + a_ch));
        LDSM_X4(b0, b1, b2, b3, lmaddr(stage_u, b_rlo, 2 * kk + b_ch));
        HMMA16(ac0[0], ac0[1], ac0[2], ac0[3], a0, a1, a2, a3, b0, b1);
        HMMA16(ac1[0], ac1[1], ac1[2], ac1[3], a0, a1, a2, a3, b2, b3);
    }

    // 3) write G (16x16 fp32)
    {
        const int r = lane >> 2, c2 = (lane & 3) * 2;
        G[r * 16 + c2]               = ac0[0];
        G[r * 16 + c2 + 1]           = ac0[1];
        G[(r + 8) * 16 + c2]         = ac0[2];
        G[(r + 8) * 16 + c2 + 1]     = ac0[3];
        G[r * 16 + 8 + c2]           = ac1[0];
        G[r * 16 + 8 + c2 + 1]       = ac1[1];
        G[(r + 8) * 16 + 8 + c2]     = ac1[2];
        G[(r + 8) * 16 + 8 + c2 + 1] = ac1[3];
    }
    __syncwarp();

    // 4) pairs lane-parallel: s = Gjj + Gkk - 2 Gjk; e = tanh(sqrt(s))
    {
        float s = G[pj1 * 16 + pj1] + G[pk1 * 16 + pk1] - 2.f * G[pj1 * 16 + pk1];
        float x = (s > 0.f) ? s * __frsqrt_rn(s) : 0.f;
        E[lane] = 1.f - __fdividef(2.f, __expf(2.f * x) + 1.f);
        if (lane < 4) {
            float s2 = G[pj2 * 16 + pj2] + G[pk2 * 16 + pk2] - 2.f * G[pj2 * 16 + pk2];
            float x2 = (s2 > 0.f) ? s2 * __frsqrt_rn(s2) : 0.f;
            E[lane + 32] = 1.f - __fdividef(2.f, __expf(2.f * x2) + 1.f);
        }
    }
    __syncwarp();

    // 5) cs[k], u, output
    float cs_[MM];
    #pragma unroll
    for (int k = 0; k < MM; ++k) {
        float a = 0.f;
        #pragma unroll
        for (int j = 0; j < MM; ++j) {
            if (j == k) continue;
            a += E[(j < k) ? pidx(j, k) : pidx(k, j)];
        }
        cs_[k] = a;
    }

    float4 u = make_float4(0.f, 0.f, 0.f, 0.f);
    #pragma unroll
    for (int m = 0; m < MM; ++m) {
        int c = lane >> 1;
        int cs2 = (c & 8) | ((c & 7) ^ (m & 7));
        uint2 raw = *reinterpret_cast<const uint2*>(
            stage + m * 256 + cs2 * 16 + (lane & 1) * 8);
        float2 f0 = __half22float2(*reinterpret_cast<const __half2*>(&raw.x));
        float2 f1 = __half22float2(*reinterpret_cast<const __half2*>(&raw.y));
        u.x = fmaf(cs_[m], f0.x, u.x);
        u.y = fmaf(cs_[m], f0.y, u.y);
        u.z = fmaf(cs_[m], f1.x, u.z);
        u.w = fmaf(cs_[m], f1.y, u.w);
    }

    float4 o;
    o.x = 0.5f * (fs.x + u.x);
    o.y = 0.5f * (fs.y + u.y);
    o.z = 0.5f * (fs.z + u.z);
    o.w = 0.5f * (fs.w + u.w);
    out4[(size_t)n * 32 + lane] = o;
}

// ----------------------------------------------------------------------------
extern "C" void kernel_launch(void* const* d_in, const int* in_sizes, int n_in,
                              void* d_out, int out_size) {
    const float* F = (const float*)d_in[0];   // [N,9,128] fp32
    const float* W = (const float*)d_in[1];   // [9,128,128] fp32
    float* out = (float*)d_out;               // [N,128] fp32
    const int N = in_sizes[0] / (MM * DD);

    cudaFuncSetAttribute(k1_gemm, cudaFuncAttributeMaxDynamicSharedMemorySize, K1_SMEM);

    k1_gemm<<<(N + 31) / 32, 256, K1_SMEM>>>(F, W, N);
    k2_phase2<<<(N + 7) / 8, 256>>>(out, N);
}

// round 17
// speedup vs baseline: 1.3230x; 1.3230x over previous
#include <cuda_runtime.h>
#include <cuda_bf16.h>
#include <cuda_fp16.h>
#include <cstdint>

#define MM 9
#define DD 128
#define NMAX 8192

// ---------------- global scratch (static, no dynamic alloc) ----------------
static __device__ __align__(128) __half g_h[NMAX * MM * DD];   // 18.9 MB fp16

// pair index tables: pair p -> (j, k), j < k
static __device__ const int PJ_d[36] =
    {0,0,0,0,0,0,0,0, 1,1,1,1,1,1,1, 2,2,2,2,2,2, 3,3,3,3,3, 4,4,4,4, 5,5,5, 6,6, 7};
static __device__ const int PK_d[36] =
    {1,2,3,4,5,6,7,8, 2,3,4,5,6,7,8, 3,4,5,6,7,8, 4,5,6,7,8, 5,6,7,8, 6,7,8, 7,8, 8};

// ---------------- helpers ---------------------------------------------------
__device__ __forceinline__ uint32_t bswz(int row, int q) {
    int c = q >> 1;
    int cs = (c & 8) | ((c & 7) ^ (row & 7));
    return (uint32_t)(row * 256 + cs * 16 + (q & 1) * 8);
}
__device__ __forceinline__ uint32_t lmaddr(uint32_t base, int row, int chunk) {
    int cs = (chunk & 8) | ((chunk & 7) ^ (row & 7));
    return base + (uint32_t)(row * 256 + cs * 16);
}
__device__ __forceinline__ uint32_t smem_u32(const void* p) {
    uint32_t a;
    asm("{ .reg .u64 t; cvta.to.shared.u64 t, %1; cvt.u32.u64 %0, t; }" : "=r"(a) : "l"(p));
    return a;
}
#define LDSM_X4(r0, r1, r2, r3, a) \
    asm volatile("ldmatrix.sync.aligned.m8n8.x4.shared.b16 {%0,%1,%2,%3}, [%4];" \
                 : "=r"(r0), "=r"(r1), "=r"(r2), "=r"(r3) : "r"(a))
#define HMMA16(d0, d1, d2, d3, a0, a1, a2, a3, b0, b1) \
    asm volatile("mma.sync.aligned.m16n8k16.row.col.f32.f16.f16.f32 " \
                 "{%0,%1,%2,%3}, {%4,%5,%6,%7}, {%8,%9}, {%0,%1,%2,%3};" \
                 : "+f"(d0), "+f"(d1), "+f"(d2), "+f"(d3) \
                 : "r"(a0), "r"(a1), "r"(a2), "r"(a3), "r"(b0), "r"(b1))

// convert one float4 -> 4 fp16, store 8B at swizzled address
__device__ __forceinline__ void st_h4(char* base, uint32_t a, float4 v) {
    __half2 h0 = __floats2half2_rn(v.x, v.y);
    __half2 h1 = __floats2half2_rn(v.z, v.w);
    uint2 h;
    h.x = *reinterpret_cast<uint32_t*>(&h0);
    h.y = *reinterpret_cast<uint32_t*>(&h1);
    *reinterpret_cast<uint2*>(base + a) = h;
}

__device__ __forceinline__ constexpr int pidx(int j, int k) {
    return j * 8 - j * (j - 1) / 2 + (k - j - 1);
}

// ---------------- K1: persistent-W single-fp16 HMMA (R15, unchanged) ---------
// grid (32, 9), 256 thr; smem: W 32K | f 16K = 48K
#define SM_WH 0
#define SM_FH 32768
#define K1_SMEM 49152
#define NTILE_STRIDE 32

__global__ void __launch_bounds__(256, 2)
k1_gemm(const float* __restrict__ F, const float* __restrict__ Wg, int N)
{
    extern __shared__ char smem[];
    const uint32_t sb = smem_u32(smem);
    const int tid  = threadIdx.x;
    const int lane = tid & 31;
    const int warp = tid >> 5;          // 0..7
    const int rg   = warp & 1;          // rows [32rg, 32rg+32)
    const int cg   = warp >> 1;         // cols [32cg, 32cg+32)
    const int m    = blockIdx.y;
    const int ntiles = (N + 63) / 64;
    const float4* Fg4 = reinterpret_cast<const float4*>(F);
    const float4* Wg4 = reinterpret_cast<const float4*>(Wg);

    int lrow[8], lq[8];
    #pragma unroll
    for (int it = 0; it < 8; ++it) {
        int s = tid + it * 256;
        lrow[it] = s >> 5; lq[it] = s & 31;
    }

    // prefetch f for first tile
    float4 fraw[8];
    {
        const int n0 = blockIdx.x * 64;
        #pragma unroll
        for (int it = 0; it < 8; ++it) {
            int n = n0 + lrow[it];
            fraw[it] = make_float4(0.f, 0.f, 0.f, 0.f);
            if (n < N) fraw[it] = Fg4[((size_t)n * MM + m) * 32 + lq[it]];
        }
    }

    // convert W_m (fp32, L2-resident) into fp16 smem, ONCE per CTA
    #pragma unroll
    for (int it = 0; it < 16; ++it) {
        int s = tid + it * 256;
        int row = s >> 5, q = s & 31;
        st_h4(smem + SM_WH, bswz(row, q), Wg4[(size_t)m * 4096 + s]);
    }
    __syncthreads();

    const int a_row0 = 32 * rg + (lane & 15);
    const int a_ch   = lane >> 4;
    const int b_rlo  = (lane & 7) + ((lane >> 4) << 3);
    const int b_ch   = (lane >> 3) & 1;

    for (int t = blockIdx.x; t < ntiles; t += NTILE_STRIDE) {
        const int n0 = t * 64;

        #pragma unroll
        for (int it = 0; it < 8; ++it)
            st_h4(smem + SM_FH, bswz(lrow[it], lq[it]), fraw[it]);
        __syncthreads();

        const int tn = t + NTILE_STRIDE;
        if (tn < ntiles) {
            const int nn0 = tn * 64;
            #pragma unroll
            for (int it = 0; it < 8; ++it) {
                int n = nn0 + lrow[it];
                fraw[it] = make_float4(0.f, 0.f, 0.f, 0.f);
                if (n < N) fraw[it] = Fg4[((size_t)n * MM + m) * 32 + lq[it]];
            }
        }

        float acc[2][4][4];
        #pragma unroll
        for (int rt = 0; rt < 2; ++rt)
            #pragma unroll
            for (int q = 0; q < 4; ++q)
                #pragma unroll
                for (int c = 0; c < 4; ++c) acc[rt][q][c] = 0.f;

        #pragma unroll
        for (int kk = 0; kk < 8; ++kk) {
            uint32_t ah[2][4], bh[2][4];
            #pragma unroll
            for (int rt = 0; rt < 2; ++rt)
                LDSM_X4(ah[rt][0], ah[rt][1], ah[rt][2], ah[rt][3],
                        lmaddr(sb + SM_FH, a_row0 + 16 * rt, 2 * kk + a_ch));
            #pragma unroll
            for (int ct = 0; ct < 2; ++ct) {
                const int brow = 32 * cg + 16 * ct + b_rlo;
                LDSM_X4(bh[ct][0], bh[ct][1], bh[ct][2], bh[ct][3],
                        lmaddr(sb + SM_WH, brow, 2 * kk + b_ch));
            }
            #pragma unroll
            for (int rt = 0; rt < 2; ++rt) {
                #pragma unroll
                for (int q = 0; q < 4; ++q) {
                    const int ct = q >> 1, h = (q & 1) * 2;
                    HMMA16(acc[rt][q][0], acc[rt][q][1], acc[rt][q][2], acc[rt][q][3],
                           ah[rt][0], ah[rt][1], ah[rt][2], ah[rt][3],
                           bh[ct][h], bh[ct][h + 1]);
                }
            }
        }

        // relu + store g as fp16
        #pragma unroll
        for (int rt = 0; rt < 2; ++rt) {
            const int r0 = n0 + 32 * rg + 16 * rt + (lane >> 2);
            const int cb = 32 * cg + (lane & 3) * 2;
            #pragma unroll
            for (int q = 0; q < 4; ++q) {
                const int col = cb + 8 * q;
                if (r0 < N) {
                    __half2 v = __floats2half2_rn(fmaxf(acc[rt][q][0], 0.f),
                                                  fmaxf(acc[rt][q][1], 0.f));
                    *reinterpret_cast<__half2*>(g_h + ((size_t)r0 * MM + m) * DD + col) = v;
                }
                if (r0 + 8 < N) {
                    __half2 v = __floats2half2_rn(fmaxf(acc[rt][q][2], 0.f),
                                                  fmaxf(acc[rt][q][3], 0.f));
                    *reinterpret_cast<__half2*>(g_h + ((size_t)(r0 + 8) * MM + m) * DD + col) = v;
                }
            }
        }
        __syncthreads();
    }
}

// ---------------- K2: Gram phase 2, 2 examples per warp interleaved ----------
// per-warp smem: stage0 2304 | stage1 2304 | G0 1024 | G1 1024 | E0 160 | E1 160
#define K2_WSTRIDE 7040
#define K2_SMEM (8 * K2_WSTRIDE)     // 56320 (dynamic)

__global__ void __launch_bounds__(256)
k2_phase2(const float* __restrict__ F, float* __restrict__ out, int N)
{
    extern __shared__ char smem2[];
    const int lane = threadIdx.x & 31;
    const int warp = threadIdx.x >> 5;
    char* base = smem2 + warp * K2_WSTRIDE;
    char* stg0 = base;
    char* stg1 = base + 2304;
    float* G0 = reinterpret_cast<float*>(base + 4608);
    float* G1 = reinterpret_cast<float*>(base + 5632);
    float* E0 = reinterpret_cast<float*>(base + 6656);
    float* E1 = reinterpret_cast<float*>(base + 6816);
    const uint32_t stg0_u = smem_u32(stg0);
    const uint32_t stg1_u = smem_u32(stg1);
    const float4* Fg4 = reinterpret_cast<const float4*>(F);
    float4* out4 = reinterpret_cast<float4*>(out);

    const int n0 = (blockIdx.x * 8 + warp) * 2;
    if (n0 >= N) return;             // warp-uniform
    const bool has1 = (n0 + 1 < N);

    // clamped ldmatrix geometry (rows >= 9 clamped to 8; those G entries unused)
    int a_row = lane & 15;           a_row = (a_row > 8) ? 8 : a_row;
    const int a_ch  = lane >> 4;
    int b_row = (lane & 7) + ((lane >> 4) << 3);
    b_row = (b_row > 8) ? 8 : b_row;
    const int b_ch  = (lane >> 3) & 1;
    const int pj1 = PJ_d[lane], pk1 = PK_d[lane];
    const int pj2 = (lane < 4) ? PJ_d[lane + 32] : 0;
    const int pk2 = (lane < 4) ? PK_d[lane + 32] : 1;

    // 0) fsum for both examples, issued first (overlaps everything below)
    float4 fs0 = Fg4[((size_t)n0 * MM) * 32 + lane];
    #pragma unroll
    for (int m = 1; m < MM; ++m) {
        float4 v = Fg4[((size_t)n0 * MM + m) * 32 + lane];
        fs0.x += v.x; fs0.y += v.y; fs0.z += v.z; fs0.w += v.w;
    }
    float4 fs1 = make_float4(0.f, 0.f, 0.f, 0.f);
    if (has1) {
        fs1 = Fg4[((size_t)(n0 + 1) * MM) * 32 + lane];
        #pragma unroll
        for (int m = 1; m < MM; ++m) {
            float4 v = Fg4[((size_t)(n0 + 1) * MM + m) * 32 + lane];
            fs1.x += v.x; fs1.y += v.y; fs1.z += v.z; fs1.w += v.w;
        }
    }

    // 1) stage g for both examples (9 x 128 fp16 = 144 x 16B each, swizzled)
    const uint4* gs0 = reinterpret_cast<const uint4*>(g_h + (size_t)n0 * MM * DD);
    const uint4* gs1 = reinterpret_cast<const uint4*>(g_h + (size_t)(n0 + 1) * MM * DD);
    #pragma unroll
    for (int i0 = 0; i0 < 5; ++i0) {
        int i = lane + i0 * 32;
        if (i < 144) {
            int row = i >> 4, c = i & 15;
            int cs_ = (c & 8) | ((c & 7) ^ (row & 7));
            uint32_t off = (uint32_t)(row * 256 + cs_ * 16);
            *reinterpret_cast<uint4*>(stg0 + off) = gs0[i];
            if (has1) *reinterpret_cast<uint4*>(stg1 + off) = gs1[i];
        }
    }
    __syncwarp();

    // 2) two interleaved Grams
    float ac[2][8];
    #pragma unroll
    for (int e = 0; e < 2; ++e)
        #pragma unroll
        for (int c = 0; c < 8; ++c) ac[e][c] = 0.f;

    #pragma unroll
    for (int kk = 0; kk < 8; ++kk) {
        uint32_t a0, a1, a2, a3, b0, b1, b2, b3;
        uint32_t c0, c1, c2, c3, d0, d1, d2, d3;
        LDSM_X4(a0, a1, a2, a3, lmaddr(stg0_u, a_row, 2 * kk + a_ch));
        LDSM_X4(b0, b1, b2, b3, lmaddr(stg0_u, b_row, 2 * kk + b_ch));
        LDSM_X4(c0, c1, c2, c3, lmaddr(stg1_u, a_row, 2 * kk + a_ch));
        LDSM_X4(d0, d1, d2, d3, lmaddr(stg1_u, b_row, 2 * kk + b_ch));
        HMMA16(ac[0][0], ac[0][1], ac[0][2], ac[0][3], a0, a1, a2, a3, b0, b1);
        HMMA16(ac[1][0], ac[1][1], ac[1][2], ac[1][3], c0, c1, c2, c3, d0, d1);
        HMMA16(ac[0][4], ac[0][5], ac[0][6], ac[0][7], a0, a1, a2, a3, b2, b3);
        HMMA16(ac[1][4], ac[1][5], ac[1][6], ac[1][7], c0, c1, c2, c3, d2, d3);
    }

    // 3) write both G (16x16 fp32)
    {
        const int r = lane >> 2, c2 = (lane & 3) * 2;
        G0[r * 16 + c2]               = ac[0][0];
        G0[r * 16 + c2 + 1]           = ac[0][1];
        G0[(r + 8) * 16 + c2]         = ac[0][2];
        G0[(r + 8) * 16 + c2 + 1]     = ac[0][3];
        G0[r * 16 + 8 + c2]           = ac[0][4];
        G0[r * 16 + 8 + c2 + 1]       = ac[0][5];
        G0[(r + 8) * 16 + 8 + c2]     = ac[0][6];
        G0[(r + 8) * 16 + 8 + c2 + 1] = ac[0][7];
        G1[r * 16 + c2]               = ac[1][0];
        G1[r * 16 + c2 + 1]           = ac[1][1];
        G1[(r + 8) * 16 + c2]         = ac[1][2];
        G1[(r + 8) * 16 + c2 + 1]     = ac[1][3];
        G1[r * 16 + 8 + c2]           = ac[1][4];
        G1[r * 16 + 8 + c2 + 1]       = ac[1][5];
        G1[(r + 8) * 16 + 8 + c2]     = ac[1][6];
        G1[(r + 8) * 16 + 8 + c2 + 1] = ac[1][7];
    }
    __syncwarp();

    // 4) edges lane-parallel for both examples (batched MUFU)
    {
        float sA0 = G0[pj1 * 16 + pj1] + G0[pk1 * 16 + pk1] - 2.f * G0[pj1 * 16 + pk1];
        float sA1 = G1[pj1 * 16 + pj1] + G1[pk1 * 16 + pk1] - 2.f * G1[pj1 * 16 + pk1];
        float xA0 = (sA0 > 0.f) ? sA0 * __frsqrt_rn(sA0) : 0.f;
        float xA1 = (sA1 > 0.f) ? sA1 * __frsqrt_rn(sA1) : 0.f;
        E0[lane] = 1.f - __fdividef(2.f, __expf(2.f * xA0) + 1.f);
        E1[lane] = 1.f - __fdividef(2.f, __expf(2.f * xA1) + 1.f);
        if (lane < 4) {
            float sB0 = G0[pj2 * 16 + pj2] + G0[pk2 * 16 + pk2] - 2.f * G0[pj2 * 16 + pk2];
            float sB1 = G1[pj2 * 16 + pj2] + G1[pk2 * 16 + pk2] - 2.f * G1[pj2 * 16 + pk2];
            float xB0 = (sB0 > 0.f) ? sB0 * __frsqrt_rn(sB0) : 0.f;
            float xB1 = (sB1 > 0.f) ? sB1 * __frsqrt_rn(sB1) : 0.f;
            E0[lane + 32] = 1.f - __fdividef(2.f, __expf(2.f * xB0) + 1.f);
            E1[lane + 32] = 1.f - __fdividef(2.f, __expf(2.f * xB1) + 1.f);
        }
    }
    __syncwarp();

    // 5) per-example: cs, u, output
    #pragma unroll
    for (int e = 0; e < 2; ++e) {
        if (e == 1 && !has1) break;
        const float* E = (e == 0) ? E0 : E1;
        char* stg = (e == 0) ? stg0 : stg1;
        float4 fs = (e == 0) ? fs0 : fs1;

        float cs_[MM];
        #pragma unroll
        for (int k = 0; k < MM; ++k) {
            float a = 0.f;
            #pragma unroll
            for (int j = 0; j < MM; ++j) {
                if (j == k) continue;
                a += E[(j < k) ? pidx(j, k) : pidx(k, j)];
            }
            cs_[k] = a;
        }

        float4 u = make_float4(0.f, 0.f, 0.f, 0.f);
        #pragma unroll
        for (int m = 0; m < MM; ++m) {
            int c = lane >> 1;
            int cs2 = (c & 8) | ((c & 7) ^ (m & 7));
            uint2 raw = *reinterpret_cast<const uint2*>(
                stg + m * 256 + cs2 * 16 + (lane & 1) * 8);
            float2 f0 = __half22float2(*reinterpret_cast<const __half2*>(&raw.x));
            float2 f1 = __half22float2(*reinterpret_cast<const __half2*>(&raw.y));
            u.x = fmaf(cs_[m], f0.x, u.x);
            u.y = fmaf(cs_[m], f0.y, u.y);
            u.z = fmaf(cs_[m], f1.x, u.z);
            u.w = fmaf(cs_[m], f1.y, u.w);
        }

        float4 o;
        o.x = 0.5f * (fs.x + u.x);
        o.y = 0.5f * (fs.y + u.y);
        o.z = 0.5f * (fs.z + u.z);
        o.w = 0.5f * (fs.w + u.w);
        out4[(size_t)(n0 + e) * 32 + lane] = o;
    }
}

// ----------------------------------------------------------------------------
extern "C" void kernel_launch(void* const* d_in, const int* in_sizes, int n_in,
                              void* d_out, int out_size) {
    const float* F = (const float*)d_in[0];   // [N,9,128] fp32
    const float* W = (const float*)d_in[1];   // [9,128,128] fp32
    float* out = (float*)d_out;               // [N,128] fp32
    const int N = in_sizes[0] / (MM * DD);

    cudaFuncSetAttribute(k1_gemm, cudaFuncAttributeMaxDynamicSharedMemorySize, K1_SMEM);
    cudaFuncSetAttribute(k2_phase2, cudaFuncAttributeMaxDynamicSharedMemorySize, K2_SMEM);

    dim3 g1(NTILE_STRIDE, MM);
    k1_gemm<<<g1, 256, K1_SMEM>>>(F, W, N);
    k2_phase2<<<(N + 15) / 16, 256, K2_SMEM>>>(F, out, N);
}